// round 9
// baseline (speedup 1.0000x reference)
#include <cuda_runtime.h>
#include <cuda_bf16.h>
#include <cstdint>

#define KC 128
#define DD 128
#define TM 128
#define TPB 512
#define NSM 148

// ---- device scratch ----
__device__ float g_part[NSM * KC];
__device__ float g_pms[NSM];
__device__ int   g_count;

// ---- smem layout (bytes) ----
#define XF_STRIDE 576
#define SM_XF0  0                     // 73728
#define SM_XF1  73728                 // 73728
#define SM_A    147456                // 32768
#define SM_B    180224                // 32768
#define SM_X2   212992                // 512
#define SM_MS   213504                // 512
#define SM_C2   214016                // 512
#define SM_IC   214528                // 512 (2/(1-c2))
#define SM_SCOL 215040                // 512
#define SM_MSUM 215552                // 8
#define SM_TOTAL 215560

__device__ __forceinline__ uint32_t smem_u32(const void* p) {
    uint32_t a;
    asm("{ .reg .u64 t; cvta.to.shared.u64 t, %1; cvt.u32.u64 %0, t; }" : "=r"(a) : "l"(p));
    return a;
}
__device__ __forceinline__ uint32_t bf2u(__nv_bfloat162 h) {
    return *reinterpret_cast<uint32_t*>(&h);
}
__device__ __forceinline__ void ldsm4(uint32_t& r0, uint32_t& r1, uint32_t& r2, uint32_t& r3,
                                      uint32_t addr) {
    asm volatile("ldmatrix.sync.aligned.m8n8.x4.shared.b16 {%0,%1,%2,%3}, [%4];"
                 : "=r"(r0), "=r"(r1), "=r"(r2), "=r"(r3) : "r"(addr));
}
__device__ __forceinline__ void mma16816(float* c, const uint32_t* a, const uint32_t* b) {
    asm volatile(
        "mma.sync.aligned.m16n8k16.row.col.f32.bf16.bf16.f32 "
        "{%0,%1,%2,%3}, {%4,%5,%6,%7}, {%8,%9}, {%0,%1,%2,%3};"
        : "+f"(c[0]), "+f"(c[1]), "+f"(c[2]), "+f"(c[3])
        : "r"(a[0]), "r"(a[1]), "r"(a[2]), "r"(a[3]), "r"(b[0]), "r"(b[1]));
}
__device__ __forceinline__ float sqrt_ap(float v) {
    float r; asm("sqrt.approx.f32 %0, %1;" : "=f"(r) : "f"(v)); return r;
}
__device__ __forceinline__ float lg2_ap(float v) {
    float r; asm("lg2.approx.f32 %0, %1;" : "=f"(r) : "f"(v)); return r;
}
__device__ __forceinline__ float rcp_ap(float v) {
    float r; asm("rcp.approx.f32 %0, %1;" : "=f"(r) : "f"(v)); return r;
}
// d = dot, xc = x2+c2, R = 2*rcp(1-x2)*rcp(1-c2), lm = ln2*mask
__device__ __forceinline__ float pdist(float d, float xc, float R, float lm) {
    float sq  = fmaxf(fmaf(d, -2.0f, xc), 0.0f);
    float arg = fmaxf(fmaf(sq, R, 1.0f), 1.0f + 1e-7f);
    float v   = arg + sqrt_ap(fmaf(arg, arg, -1.0f));
    return lg2_ap(v) * lm;
}
__device__ __forceinline__ void stage_async(uint32_t xf, const float* __restrict__ x,
                                            int tile0, int N, int tid) {
#pragma unroll
    for (int j = 0; j < 8; j++) {
        int i = tid + TPB * j;
        int row = i >> 5, c = i & 31;
        int gr = tile0 + row; if (gr >= N) gr = N - 1;
        const float* src = x + (size_t)gr * DD + c * 4;
        uint32_t dst = xf + row * XF_STRIDE + c * 16;
        asm volatile("cp.async.cg.shared.global [%0], [%1], 16;" :: "r"(dst), "l"(src));
    }
    asm volatile("cp.async.commit_group;" ::: "memory");
}

// ---- single fused kernel ----
__global__ void __launch_bounds__(TPB, 1)
dist_kernel(const float* __restrict__ x,
            const float* __restrict__ mask,
            const float* __restrict__ cw,
            float* __restrict__ out, int N, int ntiles) {
    extern __shared__ char smem[];
    const uint32_t sb = smem_u32(smem);
    const int tid = threadIdx.x, wid = tid >> 5, l = tid & 31;
    const int wr = wid & 3, wc = wid >> 2;

    float* x2s  = (float*)(smem + SM_X2);
    float* ms   = (float*)(smem + SM_MS);
    float* c2s  = (float*)(smem + SM_C2);
    float* ics  = (float*)(smem + SM_IC);
    float* scol = (float*)(smem + SM_SCOL);
    float* msum = (float*)(smem + SM_MSUM);
    float* out_node = out + KC;

    // prefetch first X tile immediately (hides centroid prep)
    int tile = blockIdx.x;
    if (tile < ntiles) stage_async(sb + SM_XF0, x, tile * TM, N, tid);
    int p = 0;

    // inline centroid prep: 16 warps x 8 rows; exp-map -> bf16 B tile + c2
#pragma unroll
    for (int r8 = 0; r8 < 8; r8++) {
        int row = wid * 8 + r8;
        float4 v = ((const float4*)(cw + (size_t)row * DD))[l];
        float ss = v.x * v.x + v.y * v.y + v.z * v.z + v.w * v.w;
#pragma unroll
        for (int o = 16; o; o >>= 1) ss += __shfl_xor_sync(0xffffffffu, ss, o);
        float norm = fmaxf(sqrtf(ss), 1e-5f);
        float s = tanhf(fminf(norm, 15.0f)) / norm;
        uint2 st;
        st.x = bf2u(__float22bfloat162_rn(make_float2(v.x * s, v.y * s)));
        st.y = bf2u(__float22bfloat162_rn(make_float2(v.z * s, v.w * s)));
        int c = l >> 1, half = l & 1;
        *(uint2*)(smem + SM_B + row * 256 + (((c ^ (row & 7)) << 4) | (half << 3))) = st;
        if (l == 0) {
            float c2 = ss * s * s;
            c2s[row] = c2;
            ics[row] = 2.0f / (1.0f - c2);
        }
    }
    if (tid < KC) scol[tid] = 0.0f;
    if (tid == 0) *msum = 0.0f;
    __syncthreads();

    const int a_row0 = wr * 32 + (l & 15);
    const int a_hi   = l >> 4;
    const int b_row0 = wc * 32 + ((l >> 4) << 3) + (l & 7);
    const int b_hi   = (l >> 3) & 1;
    const int cvrow  = wid * 8 + (l >> 2);

    for (; tile < ntiles; tile += gridDim.x, p ^= 1) {
        const int tile0 = tile * TM;
        const uint32_t xf = (p == 0) ? SM_XF0 : SM_XF1;

        asm volatile("cp.async.wait_group 0;" ::: "memory");
        __syncthreads();

        // convert: fp32 smem -> exact x2 + bf16 A tile (swizzled); load mask
        {
            int gr = tile0 + cvrow;
            if ((l & 3) == 0) ms[cvrow] = (gr < N) ? mask[gr] : 0.0f;
            float ss = 0.0f;
            const char* base = smem + xf + cvrow * XF_STRIDE;
            char* abase = smem + SM_A + cvrow * 256;
            int swr = cvrow & 7;
#pragma unroll
            for (int t = 0; t < 8; t++) {
                int c4 = (l & 3) + 4 * t;
                float4 v = *(const float4*)(base + c4 * 16);
                ss += v.x * v.x + v.y * v.y + v.z * v.z + v.w * v.w;
                uint2 st;
                st.x = bf2u(__float22bfloat162_rn(make_float2(v.x, v.y)));
                st.y = bf2u(__float22bfloat162_rn(make_float2(v.z, v.w)));
                *(uint2*)(abase + ((((c4 >> 1) ^ swr) << 4) | ((c4 & 1) << 3))) = st;
            }
            ss += __shfl_xor_sync(0xffffffffu, ss, 1);
            ss += __shfl_xor_sync(0xffffffffu, ss, 2);
            if ((l & 3) == 0) x2s[cvrow] = ss;
        }

        int nxt = tile + gridDim.x;
        if (nxt < ntiles) stage_async(sb + ((p == 0) ? SM_XF1 : SM_XF0), x, nxt * TM, N, tid);

        __syncthreads();

        if (wid == 0) {
            float wm = ms[l] + ms[l + 32] + ms[l + 64] + ms[l + 96];
#pragma unroll
            for (int o = 16; o; o >>= 1) wm += __shfl_xor_sync(0xffffffffu, wm, o);
            if (l == 0) *msum += wm;
        }

        // mainloop: warp tile 32x32, 8 k-steps
        float acc[2][4][4];
#pragma unroll
        for (int mi = 0; mi < 2; mi++)
#pragma unroll
            for (int t = 0; t < 4; t++)
#pragma unroll
                for (int u = 0; u < 4; u++) acc[mi][t][u] = 0.0f;

#pragma unroll
        for (int kk = 0; kk < 8; kk++) {
            uint32_t af[2][4];
#pragma unroll
            for (int mi = 0; mi < 2; mi++) {
                int row = a_row0 + mi * 16;
                uint32_t ad = sb + SM_A + row * 256 + ((((kk << 1) | a_hi) ^ (row & 7)) << 4);
                ldsm4(af[mi][0], af[mi][1], af[mi][2], af[mi][3], ad);
            }
            uint32_t bfr[4][2];
#pragma unroll
            for (int nt2 = 0; nt2 < 2; nt2++) {
                int nrow = b_row0 + nt2 * 16;
                uint32_t bd = sb + SM_B + nrow * 256 + ((((kk << 1) | b_hi) ^ (nrow & 7)) << 4);
                uint32_t r0, r1, r2, r3;
                ldsm4(r0, r1, r2, r3, bd);
                bfr[nt2 * 2][0] = r0;     bfr[nt2 * 2][1] = r1;
                bfr[nt2 * 2 + 1][0] = r2; bfr[nt2 * 2 + 1][1] = r3;
            }
#pragma unroll
            for (int mi = 0; mi < 2; mi++)
#pragma unroll
                for (int t = 0; t < 4; t++) mma16816(acc[mi][t], af[mi], bfr[t]);
        }

        // epilogue (no div: R = 2*rcp(1-x2)*rcp(1-c2); lm = ln2*mask)
        float cs[4][2];
#pragma unroll
        for (int t = 0; t < 4; t++) { cs[t][0] = 0.0f; cs[t][1] = 0.0f; }
#pragma unroll
        for (int mi = 0; mi < 2; mi++) {
            int r0 = wr * 32 + mi * 16 + (l >> 2);
            int r1 = r0 + 8;
            float lm0 = ms[r0] * 0.69314718f, lm1 = ms[r1] * 0.69314718f;
            float x20 = x2s[r0], x21 = x2s[r1];
            float ri0 = rcp_ap(1.0f - x20), ri1 = rcp_ap(1.0f - x21);
            bool v0ok = (tile0 + r0) < N, v1ok = (tile0 + r1) < N;
            float* p0r = out_node + (size_t)(tile0 + r0) * KC;
            float* p1r = out_node + (size_t)(tile0 + r1) * KC;
#pragma unroll
            for (int t = 0; t < 4; t++) {
                int col = wc * 32 + t * 8 + ((l & 3) << 1);
                float2 c2p = *(float2*)(c2s + col);
                float2 icp = *(float2*)(ics + col);
                float R0x = ri0 * icp.x, R0y = ri0 * icp.y;
                float R1x = ri1 * icp.x, R1y = ri1 * icp.y;
                float d0 = pdist(acc[mi][t][0], x20 + c2p.x, R0x, lm0);
                float d1 = pdist(acc[mi][t][1], x20 + c2p.y, R0y, lm0);
                float d2 = pdist(acc[mi][t][2], x21 + c2p.x, R1x, lm1);
                float d3 = pdist(acc[mi][t][3], x21 + c2p.y, R1y, lm1);
                if (v0ok) *(float2*)(p0r + col) = make_float2(d0, d1);
                if (v1ok) *(float2*)(p1r + col) = make_float2(d2, d3);
                cs[t][0] += d0 + d2;
                cs[t][1] += d1 + d3;
            }
        }
#pragma unroll
        for (int t = 0; t < 4; t++) {
#pragma unroll
            for (int o = 4; o <= 16; o <<= 1) {
                cs[t][0] += __shfl_xor_sync(0xffffffffu, cs[t][0], o);
                cs[t][1] += __shfl_xor_sync(0xffffffffu, cs[t][1], o);
            }
            if (l < 4) {
                int col = wc * 32 + t * 8 + ((l & 3) << 1);
                atomicAdd(&scol[col], cs[t][0]);
                atomicAdd(&scol[col + 1], cs[t][1]);
            }
        }
        __syncthreads();
    }

    // per-CTA partials (deterministic slots, no global atomics on values)
    if (tid < KC) g_part[blockIdx.x * KC + tid] = scol[tid];
    if (tid == 0) g_pms[blockIdx.x] = *msum;
    __threadfence();
    __syncthreads();

    // arrival: last CTA finishes graph output
    __shared__ int is_last;
    if (tid == 0) {
        int old = atomicAdd(&g_count, 1);
        is_last = (old == (int)gridDim.x - 1) ? 1 : 0;
    }
    __syncthreads();
    if (is_last) {
        __threadfence();
        if (tid == 0) {
            float tm = 0.0f;
            for (int c = 0; c < NSM; c++) tm += g_pms[c];
            *msum = tm;
        }
        __syncthreads();
        if (tid < KC) {
            float s = 0.0f;
            for (int c = 0; c < NSM; c++) s += g_part[c * KC + tid];
            out[tid] = s / *msum;
        }
        __syncthreads();
        if (tid == 0) atomicExch(&g_count, 0);   // reset for next replay
    }
}

extern "C" void kernel_launch(void* const* d_in, const int* in_sizes, int n_in,
                              void* d_out, int out_size) {
    const float* x    = (const float*)d_in[0];
    const float* mask = (const float*)d_in[1];
    const float* cw   = (const float*)d_in[2];
    const int N = in_sizes[1];
    float* out = (float*)d_out;

    cudaFuncSetAttribute(dist_kernel, cudaFuncAttributeMaxDynamicSharedMemorySize, SM_TOTAL);
    const int ntiles = (N + TM - 1) / TM;
    dist_kernel<<<NSM, TPB, SM_TOTAL>>>(x, mask, cw, out, N, ntiles);
}

// round 11
// speedup vs baseline: 1.1417x; 1.1417x over previous
#include <cuda_runtime.h>
#include <cuda_bf16.h>
#include <cstdint>

#define KC 128
#define DD 128
#define TM 64
#define TPB 256
#define NCTA 456

// ---- device scratch ----
__device__ float g_acc[KC];
__device__ float g_masksum;
__device__ int   g_count;

// ---- smem layout (bytes) ----
#define SM_A    0                 // 64*256  = 16384 (X bf16, swizzled)
#define SM_B    16384             // 128*256 = 32768 (C bf16, swizzled)
#define SM_X2   49152             // 256
#define SM_MS   49408             // 256
#define SM_C2   49664             // 512
#define SM_IC   50176             // 512
#define SM_SCOL 50688             // 512
#define SM_MSUM 51200             // 4
#define SM_FLAG 51204             // 4
#define SM_TOTAL 51208            // x3 CTAs = 153.6 KB

__device__ __forceinline__ uint32_t smem_u32(const void* p) {
    uint32_t a;
    asm("{ .reg .u64 t; cvta.to.shared.u64 t, %1; cvt.u32.u64 %0, t; }" : "=r"(a) : "l"(p));
    return a;
}
__device__ __forceinline__ uint32_t bf2u(__nv_bfloat162 h) {
    return *reinterpret_cast<uint32_t*>(&h);
}
__device__ __forceinline__ void ldsm4(uint32_t& r0, uint32_t& r1, uint32_t& r2, uint32_t& r3,
                                      uint32_t addr) {
    asm volatile("ldmatrix.sync.aligned.m8n8.x4.shared.b16 {%0,%1,%2,%3}, [%4];"
                 : "=r"(r0), "=r"(r1), "=r"(r2), "=r"(r3) : "r"(addr));
}
__device__ __forceinline__ void mma16816(float* c, const uint32_t* a, const uint32_t* b) {
    asm volatile(
        "mma.sync.aligned.m16n8k16.row.col.f32.bf16.bf16.f32 "
        "{%0,%1,%2,%3}, {%4,%5,%6,%7}, {%8,%9}, {%0,%1,%2,%3};"
        : "+f"(c[0]), "+f"(c[1]), "+f"(c[2]), "+f"(c[3])
        : "r"(a[0]), "r"(a[1]), "r"(a[2]), "r"(a[3]), "r"(b[0]), "r"(b[1]));
}
__device__ __forceinline__ float sqrt_ap(float v) {
    float r; asm("sqrt.approx.f32 %0, %1;" : "=f"(r) : "f"(v)); return r;
}
__device__ __forceinline__ float lg2_ap(float v) {
    float r; asm("lg2.approx.f32 %0, %1;" : "=f"(r) : "f"(v)); return r;
}
__device__ __forceinline__ float rcp_ap(float v) {
    float r; asm("rcp.approx.f32 %0, %1;" : "=f"(r) : "f"(v)); return r;
}
// d = dot, xc = x2+c2, R = 2*rcp(1-x2)*rcp(1-c2), lm = ln2*mask
__device__ __forceinline__ float pdist(float d, float xc, float R, float lm) {
    float sq  = fmaxf(fmaf(d, -2.0f, xc), 0.0f);
    float arg = fmaxf(fmaf(sq, R, 1.0f), 1.0f + 1e-7f);
    float v   = arg + sqrt_ap(fmaf(arg, arg, -1.0f));
    return lg2_ap(v) * lm;
}

__global__ void __launch_bounds__(TPB, 3)
dist_kernel(const float* __restrict__ x,
            const float* __restrict__ mask,
            const float* __restrict__ cw,
            float* __restrict__ out, int N, int ntiles) {
    extern __shared__ char smem[];
    const uint32_t sb = smem_u32(smem);
    const int tid = threadIdx.x, wid = tid >> 5, l = tid & 31;
    const int wr = wid & 1, wc = wid >> 1;    // warp grid 2 (rows) x 4 (cols)

    float* x2s  = (float*)(smem + SM_X2);
    float* ms   = (float*)(smem + SM_MS);
    float* c2s  = (float*)(smem + SM_C2);
    float* ics  = (float*)(smem + SM_IC);
    float* scol = (float*)(smem + SM_SCOL);
    float* msum = (float*)(smem + SM_MSUM);
    int*   flag = (int*)(smem + SM_FLAG);
    float* out_node = out + KC;

    // ---- inline centroid prep: 8 warps x 16 rows ----
#pragma unroll 2
    for (int r16 = 0; r16 < 16; r16++) {
        int row = wid * 16 + r16;
        float4 v = ((const float4*)(cw + (size_t)row * DD))[l];
        float ss = v.x * v.x + v.y * v.y + v.z * v.z + v.w * v.w;
#pragma unroll
        for (int o = 16; o; o >>= 1) ss += __shfl_xor_sync(0xffffffffu, ss, o);
        float norm = fmaxf(sqrtf(ss), 1e-5f);
        float s = tanhf(fminf(norm, 15.0f)) / norm;
        uint2 st;
        st.x = bf2u(__float22bfloat162_rn(make_float2(v.x * s, v.y * s)));
        st.y = bf2u(__float22bfloat162_rn(make_float2(v.z * s, v.w * s)));
        int c = l >> 1, half = l & 1;
        *(uint2*)(smem + SM_B + row * 256 + (((c ^ (row & 7)) << 4) | (half << 3))) = st;
        if (l == 0) {
            float c2 = ss * s * s;
            c2s[row] = c2;
            ics[row] = 2.0f / (1.0f - c2);
        }
    }
    if (tid < KC) scol[tid] = 0.0f;
    if (tid == 0) *msum = 0.0f;
    __syncthreads();

    const int a_row0 = wr * 32 + (l & 15);
    const int a_hi   = l >> 4;
    const int b_off  = ((l >> 4) << 3) + (l & 7);
    const int b_hi   = (l >> 3) & 1;

    for (int tile = blockIdx.x; tile < ntiles; tile += NCTA) {
        const int tile0 = tile * TM;

        // ---- convert: LDG fp32 -> exact x2 + bf16 A tile (swizzled) ----
#pragma unroll
        for (int j = 0; j < 8; j++) {
            int i = tid + TPB * j;            // 2048 chunks of 16B
            int row = i >> 5, c = i & 31;     // one row per warp per j
            int gr = tile0 + row; if (gr >= N) gr = N - 1;
            float4 v = ((const float4*)x)[(size_t)gr * 32 + c];
            float ss = v.x * v.x + v.y * v.y + v.z * v.z + v.w * v.w;
#pragma unroll
            for (int o = 16; o; o >>= 1) ss += __shfl_xor_sync(0xffffffffu, ss, o);
            if (l == 0) x2s[row] = ss;
            uint2 st;
            st.x = bf2u(__float22bfloat162_rn(make_float2(v.x, v.y)));
            st.y = bf2u(__float22bfloat162_rn(make_float2(v.z, v.w)));
            *(uint2*)(smem + SM_A + row * 256 +
                      ((((c >> 1) ^ (row & 7)) << 4) | ((c & 1) << 3))) = st;
        }
        if (tid < TM) {
            int gr = tile0 + tid;
            ms[tid] = (gr < N) ? mask[gr] : 0.0f;
        }
        __syncthreads();

        if (wid == 0) {
            float wm = ms[l] + ms[l + 32];
#pragma unroll
            for (int o = 16; o; o >>= 1) wm += __shfl_xor_sync(0xffffffffu, wm, o);
            if (l == 0) *msum += wm;
        }

        // ---- two column passes: warp tile 32 rows x 16 cols ----
#pragma unroll 1
        for (int pass = 0; pass < 2; pass++) {
            float acc[2][2][4];
#pragma unroll
            for (int mi = 0; mi < 2; mi++)
#pragma unroll
                for (int t = 0; t < 2; t++)
#pragma unroll
                    for (int u = 0; u < 4; u++) acc[mi][t][u] = 0.0f;

            const int nrow = pass * 64 + wc * 16 + b_off;
            const uint32_t bd0 = sb + SM_B + nrow * 256;

#pragma unroll
            for (int kk = 0; kk < 8; kk++) {
                uint32_t af[2][4];
#pragma unroll
                for (int mi = 0; mi < 2; mi++) {
                    int row = a_row0 + mi * 16;
                    uint32_t ad = sb + SM_A + row * 256
                                + ((((kk << 1) | a_hi) ^ (row & 7)) << 4);
                    ldsm4(af[mi][0], af[mi][1], af[mi][2], af[mi][3], ad);
                }
                uint32_t bfr[2][2];
                {
                    uint32_t bdk = bd0 + ((((kk << 1) | b_hi) ^ (nrow & 7)) << 4);
                    uint32_t r0, r1, r2, r3;
                    ldsm4(r0, r1, r2, r3, bdk);
                    bfr[0][0] = r0; bfr[0][1] = r1;
                    bfr[1][0] = r2; bfr[1][1] = r3;
                }
#pragma unroll
                for (int mi = 0; mi < 2; mi++)
#pragma unroll
                    for (int t = 0; t < 2; t++) mma16816(acc[mi][t], af[mi], bfr[t]);
            }

            // epilogue for this 64-col half
            float cs[2][2];
            cs[0][0] = cs[0][1] = cs[1][0] = cs[1][1] = 0.0f;
#pragma unroll
            for (int mi = 0; mi < 2; mi++) {
                int r0 = wr * 32 + mi * 16 + (l >> 2);
                int r1 = r0 + 8;
                float lm0 = ms[r0] * 0.69314718f, lm1 = ms[r1] * 0.69314718f;
                float x20 = x2s[r0], x21 = x2s[r1];
                float ri0 = rcp_ap(1.0f - x20), ri1 = rcp_ap(1.0f - x21);
                bool v0ok = (tile0 + r0) < N, v1ok = (tile0 + r1) < N;
                float* p0r = out_node + (size_t)(tile0 + r0) * KC;
                float* p1r = out_node + (size_t)(tile0 + r1) * KC;
#pragma unroll
                for (int t = 0; t < 2; t++) {
                    int col = pass * 64 + wc * 16 + t * 8 + ((l & 3) << 1);
                    float2 c2p = *(float2*)(c2s + col);
                    float2 icp = *(float2*)(ics + col);
                    float d0 = pdist(acc[mi][t][0], x20 + c2p.x, ri0 * icp.x, lm0);
                    float d1 = pdist(acc[mi][t][1], x20 + c2p.y, ri0 * icp.y, lm0);
                    float d2 = pdist(acc[mi][t][2], x21 + c2p.x, ri1 * icp.x, lm1);
                    float d3 = pdist(acc[mi][t][3], x21 + c2p.y, ri1 * icp.y, lm1);
                    if (v0ok) *(float2*)(p0r + col) = make_float2(d0, d1);
                    if (v1ok) *(float2*)(p1r + col) = make_float2(d2, d3);
                    cs[t][0] += d0 + d2;
                    cs[t][1] += d1 + d3;
                }
            }
#pragma unroll
            for (int t = 0; t < 2; t++) {
#pragma unroll
                for (int o = 4; o <= 16; o <<= 1) {
                    cs[t][0] += __shfl_xor_sync(0xffffffffu, cs[t][0], o);
                    cs[t][1] += __shfl_xor_sync(0xffffffffu, cs[t][1], o);
                }
                if (l < 4) {
                    int col = pass * 64 + wc * 16 + t * 8 + ((l & 3) << 1);
                    atomicAdd(&scol[col], cs[t][0]);
                    atomicAdd(&scol[col + 1], cs[t][1]);
                }
            }
        }
        __syncthreads();   // protect A/ms/x2s before next tile's convert
    }

    // ---- flush partials ----
    if (tid < KC) atomicAdd(&g_acc[tid], scol[tid]);
    if (tid == 0) atomicAdd(&g_masksum, *msum);
    __threadfence();
    __syncthreads();
    if (tid == 0) {
        int old = atomicAdd(&g_count, 1);
        *flag = (old == NCTA - 1) ? 1 : 0;
    }
    __syncthreads();
    if (*flag) {
        __threadfence();
        if (tid < KC) {
            float s  = atomicAdd(&g_acc[tid], 0.0f);      // coherent read
            float tm = atomicAdd(&g_masksum, 0.0f);
            out[tid] = s / tm;
        }
        __syncthreads();
        if (tid < KC) g_acc[tid] = 0.0f;                  // reset for next replay
        if (tid == 0) { g_masksum = 0.0f; atomicExch(&g_count, 0); }
    }
}

extern "C" void kernel_launch(void* const* d_in, const int* in_sizes, int n_in,
                              void* d_out, int out_size) {
    const float* x    = (const float*)d_in[0];
    const float* mask = (const float*)d_in[1];
    const float* cw   = (const float*)d_in[2];
    const int N = in_sizes[1];
    float* out = (float*)d_out;

    cudaFuncSetAttribute(dist_kernel, cudaFuncAttributeMaxDynamicSharedMemorySize, SM_TOTAL);
    const int ntiles = (N + TM - 1) / TM;
    dist_kernel<<<NCTA, TPB, SM_TOTAL>>>(x, mask, cw, out, N, ntiles);
}